// round 5
// baseline (speedup 1.0000x reference)
#include <cuda_runtime.h>

#define NSLOPE 0.2f
#define NMAX   50048
#define EMAX   655360

// ---- device scratch (no runtime allocation allowed) ----
__device__ float g_h[NMAX * 128];     // h = in @ W
__device__ float g_y[NMAX * 128];     // layer output (input to next layer)
__device__ float g_o2[NMAX * 64];     // final pre-log-softmax
__device__ float g_as[NMAX];          // h . a_src per node
__device__ float g_ad[NMAX];          // h . a_dst per node
__device__ int   g_start[NMAX + 1];   // CSR row starts (by dst)
__device__ int   g_cur[NMAX];         // scatter cursors
__device__ int   g_csr[EMAX];         // src node per CSR slot
__device__ int   g_bsum[256];         // scan block sums

// ========================== CSR build ==========================

__global__ void k_deg_init(int n) {
    int i = blockIdx.x * 256 + threadIdx.x;
    if (i < n) g_start[i] = 1;  // self-loop counted up front
}

__global__ void k_deg_count(const int* __restrict__ dst, int e) {
    int i = blockIdx.x * 256 + threadIdx.x;
    if (i < e) atomicAdd(&g_start[dst[i]], 1);
}

// exclusive scan, 1024 elements per block (256 thr x 4)
__global__ void k_scan1(int n) {
    __shared__ int s[256];
    int tid = threadIdx.x;
    int base = blockIdx.x * 1024 + tid * 4;
    int v0 = 0, v1 = 0, v2 = 0, v3 = 0;
    if (base + 0 < n) v0 = g_start[base + 0];
    if (base + 1 < n) v1 = g_start[base + 1];
    if (base + 2 < n) v2 = g_start[base + 2];
    if (base + 3 < n) v3 = g_start[base + 3];
    int tot = v0 + v1 + v2 + v3;
    s[tid] = tot;
    __syncthreads();
    for (int off = 1; off < 256; off <<= 1) {
        int a = s[tid];
        int b = (tid >= off) ? s[tid - off] : 0;
        __syncthreads();
        s[tid] = a + b;
        __syncthreads();
    }
    int excl = s[tid] - tot;
    if (base + 0 < n) g_start[base + 0] = excl;
    if (base + 1 < n) g_start[base + 1] = excl + v0;
    if (base + 2 < n) g_start[base + 2] = excl + v0 + v1;
    if (base + 3 < n) g_start[base + 3] = excl + v0 + v1 + v2;
    if (tid == 255) g_bsum[blockIdx.x] = s[255];
}

__global__ void k_scan2(int nb) {
    __shared__ int s[256];
    int tid = threadIdx.x;
    int v = (tid < nb) ? g_bsum[tid] : 0;
    s[tid] = v;
    __syncthreads();
    for (int off = 1; off < 256; off <<= 1) {
        int a = s[tid];
        int b = (tid >= off) ? s[tid - off] : 0;
        __syncthreads();
        s[tid] = a + b;
        __syncthreads();
    }
    if (tid < nb) g_bsum[tid] = s[tid] - v;  // exclusive block offsets
}

__global__ void k_scan3(int n, int total) {
    int i = blockIdx.x * 256 + threadIdx.x;
    if (i < n) g_start[i] += g_bsum[i >> 10];
    if (i == 0) g_start[n] = total;
}

__global__ void k_self(int n) {
    int i = blockIdx.x * 256 + threadIdx.x;
    if (i < n) {
        g_csr[g_start[i]] = i;  // self-loop occupies slot 0 of each segment
        g_cur[i] = 1;
    }
}

__global__ void k_scatter(const int* __restrict__ src, const int* __restrict__ dst, int e) {
    int i = blockIdx.x * 256 + threadIdx.x;
    if (i < e) {
        int d = dst[i];
        int p = atomicAdd(&g_cur[d], 1);
        g_csr[g_start[d] + p] = src[i];
    }
}

// ========================== GEMM: H = A @ W ==========================
// A: [M,128] row-major, W: [128,BN] row-major, H: [M,BN]
// 64 x BN tile per block of 256 threads; 8-deep K chunks via smem.

template <int BN>
__global__ void k_gemm(const float* __restrict__ A, const float* __restrict__ W,
                       float* __restrict__ H, int M) {
    constexpr int TX = BN / 4;     // threads along cols (32 or 16)
    constexpr int TY = 256 / TX;   // row groups (8 or 16)
    constexpr int RPT = 64 / TY;   // rows per thread (8 or 4)
    __shared__ float Xs[64][8];
    __shared__ float Ws[8][BN];
    int tid = threadIdx.x;
    int tx = tid % TX, ty = tid / TX;
    int row0 = blockIdx.x * 64;
    float acc[RPT][4];
#pragma unroll
    for (int j = 0; j < RPT; j++) {
        acc[j][0] = acc[j][1] = acc[j][2] = acc[j][3] = 0.f;
    }
    for (int k0 = 0; k0 < 128; k0 += 8) {
#pragma unroll
        for (int t = 0; t < 2; t++) {
            int i = tid + t * 256;
            int r = i >> 3, kk = i & 7;
            int gr = row0 + r;
            Xs[r][kk] = (gr < M) ? A[(size_t)gr * 128 + k0 + kk] : 0.f;
        }
#pragma unroll
        for (int t = 0; t < (8 * BN) / 256; t++) {
            int i = tid + t * 256;
            Ws[i / BN][i % BN] = W[(size_t)(k0 + i / BN) * BN + (i % BN)];
        }
        __syncthreads();
#pragma unroll
        for (int kk = 0; kk < 8; kk++) {
            float4 w = *(const float4*)&Ws[kk][tx * 4];
#pragma unroll
            for (int j = 0; j < RPT; j++) {
                float a = Xs[ty + j * TY][kk];
                acc[j][0] += a * w.x;
                acc[j][1] += a * w.y;
                acc[j][2] += a * w.z;
                acc[j][3] += a * w.w;
            }
        }
        __syncthreads();
    }
#pragma unroll
    for (int j = 0; j < RPT; j++) {
        int r = row0 + ty + j * TY;
        if (r < M) {
            float4 o = make_float4(acc[j][0], acc[j][1], acc[j][2], acc[j][3]);
            *(float4*)&H[(size_t)r * BN + tx * 4] = o;
        }
    }
}

// ================= per-node attention dots: h.a_src, h.a_dst =================

template <int D>
__global__ void k_attn(const float* __restrict__ h, const float* __restrict__ a_s,
                       const float* __restrict__ a_d, int n) {
    int warp = threadIdx.x >> 5, lane = threadIdx.x & 31;
    int v = blockIdx.x * 8 + warp;
    if (v >= n) return;
    float sa = 0.f, sd = 0.f;
#pragma unroll
    for (int f = lane; f < D; f += 32) {
        float x = h[(size_t)v * D + f];
        sa += x * a_s[f];
        sd += x * a_d[f];
    }
#pragma unroll
    for (int o = 16; o; o >>= 1) {
        sa += __shfl_xor_sync(0xffffffffu, sa, o);
        sd += __shfl_xor_sync(0xffffffffu, sd, o);
    }
    if (lane == 0) {
        g_as[v] = sa;
        g_ad[v] = sd;
    }
}

// ============ warp-per-dst-node segment softmax + weighted gather ============

template <int D, bool SILU>
__global__ void k_agg(const float* __restrict__ h, const float* __restrict__ bias,
                      float* __restrict__ out, int n) {
    constexpr int MAXDEG = 128;
    constexpr int FP = D / 32;  // floats per lane (4 or 2)
    __shared__ float wsh[4][MAXDEG];
    __shared__ int ssh[4][MAXDEG];
    int warp = threadIdx.x >> 5, lane = threadIdx.x & 31;
    int d = blockIdx.x * 4 + warp;
    if (d >= n) return;
    int st = g_start[d];
    int deg = g_start[d + 1] - st;
    float ad = g_ad[d];
    int f = lane * FP;
    float acc[FP];
#pragma unroll
    for (int j = 0; j < FP; j++) acc[j] = 0.f;

    if (deg <= MAXDEG) {
        // phase 1: lanes parallel over neighbors — alpha, max, exp, denom
        float m = -1e30f;
        for (int i = lane; i < deg; i += 32) {
            int s = g_csr[st + i];
            ssh[warp][i] = s;
            float al = g_as[s] + ad;
            al = al > 0.f ? al : NSLOPE * al;
            wsh[warp][i] = al;
            m = fmaxf(m, al);
        }
#pragma unroll
        for (int o = 16; o; o >>= 1) m = fmaxf(m, __shfl_xor_sync(0xffffffffu, m, o));
        __syncwarp();
        float den = 0.f;
        for (int i = lane; i < deg; i += 32) {
            float w = __expf(wsh[warp][i] - m);
            wsh[warp][i] = w;
            den += w;
        }
#pragma unroll
        for (int o = 16; o; o >>= 1) den += __shfl_xor_sync(0xffffffffu, den, o);
        __syncwarp();
        float inv = 1.f / den;
        // phase 2: whole warp gathers each neighbor's h row (coalesced, L2-resident)
        for (int i = 0; i < deg; i++) {
            int s = ssh[warp][i];
            float c = wsh[warp][i] * inv;
            const float* hp = h + (size_t)s * D + f;
            if constexpr (FP == 4) {
                float4 hv = *(const float4*)hp;
                acc[0] += c * hv.x;
                acc[1] += c * hv.y;
                acc[2] += c * hv.z;
                acc[3] += c * hv.w;
            } else {
                float2 hv = *(const float2*)hp;
                acc[0] += c * hv.x;
                acc[1] += c * hv.y;
            }
        }
    } else {
        // fallback: online softmax, lanes redundant on scalars (never expected)
        float m = -1e30f, den = 0.f;
        for (int i = 0; i < deg; i++) {
            int s = g_csr[st + i];
            float al = g_as[s] + ad;
            al = al > 0.f ? al : NSLOPE * al;
            float nm = fmaxf(m, al);
            float sc = __expf(m - nm);
            float w = __expf(al - nm);
            den = den * sc + w;
            const float* hp = h + (size_t)s * D + f;
#pragma unroll
            for (int j = 0; j < FP; j++) acc[j] = acc[j] * sc + w * hp[j];
            m = nm;
        }
        float inv = 1.f / den;
#pragma unroll
        for (int j = 0; j < FP; j++) acc[j] *= inv;
    }

#pragma unroll
    for (int j = 0; j < FP; j++) {
        float v = acc[j] + bias[f + j];
        if (SILU) v = v / (1.f + __expf(-v));
        out[(size_t)d * D + f + j] = v;
    }
}

// ========================== log_softmax over 64 cols ==========================

__global__ void k_lsm(const float* __restrict__ in, float* __restrict__ out, int n) {
    int warp = threadIdx.x >> 5, lane = threadIdx.x & 31;
    int r = blockIdx.x * 8 + warp;
    if (r >= n) return;
    float2 v = *(const float2*)&in[(size_t)r * 64 + lane * 2];
    float m = fmaxf(v.x, v.y);
#pragma unroll
    for (int o = 16; o; o >>= 1) m = fmaxf(m, __shfl_xor_sync(0xffffffffu, m, o));
    float s = __expf(v.x - m) + __expf(v.y - m);
#pragma unroll
    for (int o = 16; o; o >>= 1) s += __shfl_xor_sync(0xffffffffu, s, o);
    float l = m + __logf(s);
    float2 o2 = make_float2(v.x - l, v.y - l);
    *(float2*)&out[(size_t)r * 64 + lane * 2] = o2;
}

// ========================== host launcher ==========================

extern "C" void kernel_launch(void* const* d_in, const int* in_sizes, int n_in,
                              void* d_out, int out_size) {
    const float* x   = (const float*)d_in[0];
    const int*   ei  = (const int*)d_in[1];
    const float* W0  = (const float*)d_in[2];
    const float* as0 = (const float*)d_in[3];
    const float* ad0 = (const float*)d_in[4];
    const float* b0  = (const float*)d_in[5];
    const float* W1  = (const float*)d_in[6];
    const float* as1 = (const float*)d_in[7];
    const float* ad1 = (const float*)d_in[8];
    const float* b1  = (const float*)d_in[9];
    const float* W2  = (const float*)d_in[10];
    const float* as2 = (const float*)d_in[11];
    const float* ad2 = (const float*)d_in[12];
    const float* b2  = (const float*)d_in[13];

    int n = in_sizes[0] / 128;  // 50000
    int e = in_sizes[1] / 2;    // 600000
    const int* src = ei;
    const int* dst = ei + e;
    float* outp = (float*)d_out;

    float *ph, *py, *po2;
    cudaGetSymbolAddress((void**)&ph, g_h);
    cudaGetSymbolAddress((void**)&py, g_y);
    cudaGetSymbolAddress((void**)&po2, g_o2);

    int nbN = (n + 255) / 256;
    int nbE = (e + 255) / 256;
    int nbS = (n + 1023) / 1024;
    int nbG = (n + 63) / 64;
    int nbW = (n + 7) / 8;
    int nbA = (n + 3) / 4;

    // CSR by dst (includes self-loops at segment head)
    k_deg_init<<<nbN, 256>>>(n);
    k_deg_count<<<nbE, 256>>>(dst, e);
    k_scan1<<<nbS, 256>>>(n);
    k_scan2<<<1, 256>>>(nbS);
    k_scan3<<<nbN, 256>>>(n, e + n);
    k_self<<<nbN, 256>>>(n);
    k_scatter<<<nbE, 256>>>(src, dst, e);

    // layer 0: 128 -> 128, SiLU
    k_gemm<128><<<nbG, 256>>>(x, W0, ph, n);
    k_attn<128><<<nbW, 256>>>(ph, as0, ad0, n);
    k_agg<128, true><<<nbA, 128>>>(ph, b0, py, n);

    // layer 1: 128 -> 128, SiLU
    k_gemm<128><<<nbG, 256>>>(py, W1, ph, n);
    k_attn<128><<<nbW, 256>>>(ph, as1, ad1, n);
    k_agg<128, true><<<nbA, 128>>>(ph, b1, py, n);

    // layer 2: 128 -> 64, no SiLU, then log_softmax
    k_gemm<64><<<nbG, 256>>>(py, W2, ph, n);
    k_attn<64><<<nbW, 256>>>(ph, as2, ad2, n);
    k_agg<64, false><<<nbA, 128>>>(ph, b2, po2, n);
    k_lsm<<<nbW, 256>>>(po2, outp, n);
}